// round 3
// baseline (speedup 1.0000x reference)
#include <cuda_runtime.h>
#include <cuda_bf16.h>
#include <cstdint>
#include <cstddef>

// ---------------- problem constants ----------------
#define DD        1024
#define BB        4096
#define RROWS     8192
#define ROW_BYTES 2048u               // 1024 bf16
#define TILE      128
#define TILES_DIM 64
#define NKCHUNKS  16                  // K=1024 in chunks of 64 bf16 (128B/row)
#define CHUNK_BYTES 16384             // 128 rows * 128 B
#define STAGE_BYTES (2 * CHUNK_BYTES) // A + B
#define SMEM_SZ   (2 * STAGE_BYTES)   // 2 stages = 64 KB dynamic

#define TWO_LOG2E 2.8853900817779268f // exp(2x) = 2^(x * 2*log2 e)
#define E2_CONST  7.38905609893065f

// ---------------- device scratch (no allocation) ----------------
__device__ __nv_bfloat16 g_rep[RROWS * DD];   // 16 MB normalized rows (bf16)
__device__ float g_pos[BB];
__device__ float g_rowsum[RROWS];

// ---------------- helpers ----------------
__device__ __forceinline__ uint32_t smem_u32(const void* p) {
    uint32_t a;
    asm("{ .reg .u64 t; cvta.to.shared.u64 t, %1; cvt.u32.u64 %0, t; }" : "=r"(a) : "l"(p));
    return a;
}
__device__ __forceinline__ float ex2f(float x) {
    float y; asm("ex2.approx.ftz.f32 %0, %1;" : "=f"(y) : "f"(x)); return y;
}
__device__ __forceinline__ uint32_t swz(uint32_t bo) {   // SW128: XOR 16B-chunk sel with row low bits
    return bo ^ ((bo >> 3) & 0x70u);
}
__device__ __forceinline__ void cp_async16(uint32_t dst, const void* src) {
    asm volatile("cp.async.cg.shared.global [%0], [%1], 16;"
                 :: "r"(dst), "l"(__cvta_generic_to_global(src)) : "memory");
}
#define CP_COMMIT() asm volatile("cp.async.commit_group;" ::: "memory")
#define CP_WAIT(n)  asm volatile("cp.async.wait_group %0;" :: "n"(n) : "memory")

__device__ __forceinline__ void ldsm4(uint32_t* r, uint32_t addr) {
    asm volatile("ldmatrix.sync.aligned.m8n8.x4.shared.b16 {%0,%1,%2,%3}, [%4];"
                 : "=r"(r[0]), "=r"(r[1]), "=r"(r[2]), "=r"(r[3]) : "r"(addr));
}
__device__ __forceinline__ void mma16816(float* d, const uint32_t* a, const uint32_t* b) {
    asm volatile(
        "mma.sync.aligned.m16n8k16.row.col.f32.bf16.bf16.f32 "
        "{%0,%1,%2,%3}, {%4,%5,%6,%7}, {%8,%9}, {%0,%1,%2,%3};"
        : "+f"(d[0]), "+f"(d[1]), "+f"(d[2]), "+f"(d[3])
        : "r"(a[0]), "r"(a[1]), "r"(a[2]), "r"(a[3]), "r"(b[0]), "r"(b[1]));
}

// ---------------- kernel 1: normalize + positives + rowsum zero ----------------
__global__ void __launch_bounds__(256) normalize_kernel(const float4* __restrict__ p1,
                                                        const float4* __restrict__ p2) {
    int row = blockIdx.x, tid = threadIdx.x;
    float4 a = p1[row * 256 + tid];
    float4 b = p2[row * 256 + tid];
    float s11 = a.x * a.x + a.y * a.y + a.z * a.z + a.w * a.w;
    float s22 = b.x * b.x + b.y * b.y + b.z * b.z + b.w * b.w;
    float s12 = a.x * b.x + a.y * b.y + a.z * b.z + a.w * b.w;
    #pragma unroll
    for (int o = 16; o; o >>= 1) {
        s11 += __shfl_xor_sync(0xFFFFFFFFu, s11, o);
        s22 += __shfl_xor_sync(0xFFFFFFFFu, s22, o);
        s12 += __shfl_xor_sync(0xFFFFFFFFu, s12, o);
    }
    __shared__ float sh[3][8];
    int w = tid >> 5, l = tid & 31;
    if (l == 0) { sh[0][w] = s11; sh[1][w] = s22; sh[2][w] = s12; }
    __syncthreads();
    if (tid == 0) {
        float t11 = 0.f, t22 = 0.f, t12 = 0.f;
        #pragma unroll
        for (int i = 0; i < 8; i++) { t11 += sh[0][i]; t22 += sh[1][i]; t12 += sh[2][i]; }
        float i1 = rsqrtf(t11), i2 = rsqrtf(t22);
        sh[0][0] = i1; sh[1][0] = i2;
        g_pos[row] = t12 * i1 * i2;
        g_rowsum[row] = 0.f;
        g_rowsum[row + BB] = 0.f;
    }
    __syncthreads();
    float i1 = sh[0][0], i2 = sh[1][0];

    struct alignas(8) bf16x4 { __nv_bfloat162 lo, hi; };
    bf16x4 va, vb;
    va.lo = __floats2bfloat162_rn(a.x * i1, a.y * i1);
    va.hi = __floats2bfloat162_rn(a.z * i1, a.w * i1);
    vb.lo = __floats2bfloat162_rn(b.x * i2, b.y * i2);
    vb.hi = __floats2bfloat162_rn(b.z * i2, b.w * i2);
    bf16x4* rep4 = reinterpret_cast<bf16x4*>(g_rep);
    rep4[row * 256 + tid]        = va;
    rep4[(row + BB) * 256 + tid] = vb;
}

// ---------------- kernel 2: symmetric bf16 mma.sync GEMM + exp rowsums ----------------
__global__ void __launch_bounds__(256, 2) gemm_kernel() {
    const int j = blockIdx.x;   // n-tile block (columns)
    const int i = blockIdx.y;   // m-tile block (rows)
    if (j < i) return;          // upper triangle only

    extern __shared__ char smem[];
    __shared__ float rowbuf[128];
    __shared__ float colbuf[128];
    uint32_t sbase = smem_u32(smem);

    const int tid = threadIdx.x, wid = tid >> 5, lane = tid & 31;
    const int wm = wid >> 2, wn = wid & 3;        // warp grid 2 (M) x 4 (N)
    const int q = lane >> 3, r = lane & 7;        // ldmatrix lane decode

    if (tid < 128) rowbuf[tid] = 0.f;
    else           colbuf[tid - 128] = 0.f;

    const char* repc = reinterpret_cast<const char*>(g_rep);
    const char* abase = repc + (size_t)i * (TILE * (size_t)ROW_BYTES);
    const char* bbase = repc + (size_t)j * (TILE * (size_t)ROW_BYTES);

    // per-thread cp.async granule map: 2048 x 16B per chunk-pair, 8 per thread
    uint32_t dsto[8], srco[8]; const char* sbas[8];
    #pragma unroll
    for (int t = 0; t < 8; t++) {
        int g   = tid + t * 256;
        int ab  = g >> 10;
        int idx = g & 1023;
        int row = idx >> 3, c16 = idx & 7;
        dsto[t] = (uint32_t)ab * CHUNK_BYTES + swz((uint32_t)row * 128u + (uint32_t)c16 * 16u);
        srco[t] = (uint32_t)row * ROW_BYTES + (uint32_t)c16 * 16u;
        sbas[t] = ab ? bbase : abase;
    }

    float acc[4][4][4];
    #pragma unroll
    for (int mi = 0; mi < 4; mi++)
        #pragma unroll
        for (int ni = 0; ni < 4; ni++)
            #pragma unroll
            for (int c = 0; c < 4; c++) acc[mi][ni][c] = 0.f;

    // prologue: chunk 0 into stage 0
    #pragma unroll
    for (int t = 0; t < 8; t++) cp_async16(sbase + dsto[t], sbas[t] + srco[t]);
    CP_COMMIT();

    // ldmatrix per-lane static address parts
    const uint32_t aRow = (uint32_t)(wm * 64 + (q & 1) * 8 + r);
    const uint32_t aKof = (uint32_t)((q >> 1) * 16);
    const uint32_t bRow0 = (uint32_t)(wn * 32 + (q >> 1) * 8 + r);   // pair p adds p*16
    const uint32_t bKof = (uint32_t)((q & 1) * 16);

    for (int kc = 0; kc < NKCHUNKS; kc++) {
        uint32_t nstg = sbase + (uint32_t)((kc + 1) & 1) * STAGE_BYTES;
        if (kc < NKCHUNKS - 1) {
            uint32_t kb = (uint32_t)(kc + 1) * 128u;
            #pragma unroll
            for (int t = 0; t < 8; t++) cp_async16(nstg + dsto[t], sbas[t] + srco[t] + kb);
            CP_COMMIT();
            CP_WAIT(1);
        } else {
            CP_WAIT(0);
        }
        __syncthreads();

        uint32_t stg = sbase + (uint32_t)(kc & 1) * STAGE_BYTES;
        #pragma unroll
        for (int ks = 0; ks < 4; ks++) {
            uint32_t af[4][4], bf[4][2];
            #pragma unroll
            for (int mi = 0; mi < 4; mi++) {
                uint32_t bo = (aRow + (uint32_t)(mi * 16)) * 128u + (uint32_t)(ks * 32) + aKof;
                ldsm4(af[mi], stg + swz(bo));
            }
            #pragma unroll
            for (int p = 0; p < 2; p++) {
                uint32_t bo = (bRow0 + (uint32_t)(p * 16)) * 128u + (uint32_t)(ks * 32) + bKof;
                uint32_t t4[4];
                ldsm4(t4, stg + CHUNK_BYTES + swz(bo));
                bf[2 * p][0] = t4[0]; bf[2 * p][1] = t4[1];
                bf[2 * p + 1][0] = t4[2]; bf[2 * p + 1][1] = t4[3];
            }
            #pragma unroll
            for (int mi = 0; mi < 4; mi++)
                #pragma unroll
                for (int ni = 0; ni < 4; ni++)
                    mma16816(acc[mi][ni], af[mi], bf[ni]);
        }
        __syncthreads();
    }

    // ---- epilogue: exp, then row sums (block i) and col sums (block j) ----
    #pragma unroll
    for (int mi = 0; mi < 4; mi++)
        #pragma unroll
        for (int ni = 0; ni < 4; ni++)
            #pragma unroll
            for (int c = 0; c < 4; c++)
                acc[mi][ni][c] = ex2f(acc[mi][ni][c] * TWO_LOG2E);

    // row sums: reg layout per mma tile: {c0 rowLo, c1 rowLo, c0 rowHi, c1 rowHi}
    #pragma unroll
    for (int mi = 0; mi < 4; mi++) {
        #pragma unroll
        for (int rs = 0; rs < 2; rs++) {
            float v = 0.f;
            #pragma unroll
            for (int ni = 0; ni < 4; ni++) v += acc[mi][ni][rs * 2] + acc[mi][ni][rs * 2 + 1];
            v += __shfl_xor_sync(0xFFFFFFFFu, v, 1);
            v += __shfl_xor_sync(0xFFFFFFFFu, v, 2);
            if ((lane & 3) == 0)
                atomicAdd(&rowbuf[wm * 64 + mi * 16 + rs * 8 + (lane >> 2)], v);
        }
    }
    // col sums (only off-diagonal tiles — diagonal would double count)
    if (i != j) {
        #pragma unroll
        for (int ni = 0; ni < 4; ni++) {
            #pragma unroll
            for (int cs = 0; cs < 2; cs++) {
                float v = 0.f;
                #pragma unroll
                for (int mi = 0; mi < 4; mi++) v += acc[mi][ni][cs] + acc[mi][ni][2 + cs];
                v += __shfl_xor_sync(0xFFFFFFFFu, v, 4);
                v += __shfl_xor_sync(0xFFFFFFFFu, v, 8);
                v += __shfl_xor_sync(0xFFFFFFFFu, v, 16);
                if ((lane >> 2) == 0)
                    atomicAdd(&colbuf[wn * 32 + ni * 8 + (lane & 3) * 2 + cs], v);
            }
        }
    }
    __syncthreads();
    if (tid < 128) atomicAdd(&g_rowsum[i * TILE + tid], rowbuf[tid]);
    else if (i != j) atomicAdd(&g_rowsum[j * TILE + (tid - 128)], colbuf[tid - 128]);
}

// ---------------- kernel 3: finalize loss ----------------
__global__ void __launch_bounds__(256) finalize_kernel(float* __restrict__ out) {
    int tid = threadIdx.x;
    float s = 0.f;
    for (int r = tid; r < RROWS; r += 256) {
        float den = g_rowsum[r] - E2_CONST;   // remove self-similarity term
        float pos = g_pos[r & (BB - 1)];
        s += logf(den) - 2.f * pos;
    }
    #pragma unroll
    for (int o = 16; o; o >>= 1) s += __shfl_xor_sync(0xFFFFFFFFu, s, o);
    __shared__ float sh[8];
    if ((tid & 31) == 0) sh[tid >> 5] = s;
    __syncthreads();
    if (tid == 0) {
        float t = 0.f;
        #pragma unroll
        for (int k = 0; k < 8; k++) t += sh[k];
        out[0] = t / (float)RROWS;
    }
}

// ---------------- launch ----------------
extern "C" void kernel_launch(void* const* d_in, const int* in_sizes, int n_in,
                              void* d_out, int out_size) {
    const float* p1 = (const float*)d_in[0];
    const float* p2 = (const float*)d_in[1];
    float* out = (float*)d_out;

    cudaFuncSetAttribute(gemm_kernel, cudaFuncAttributeMaxDynamicSharedMemorySize, SMEM_SZ);

    normalize_kernel<<<BB, 256>>>((const float4*)p1, (const float4*)p2);
    dim3 grid(TILES_DIM, TILES_DIM);
    gemm_kernel<<<grid, 256, SMEM_SZ>>>();
    finalize_kernel<<<1, 256>>>(out);
}